// round 6
// baseline (speedup 1.0000x reference)
#include <cuda_runtime.h>

#define NN 32
#define DD 128
#define SS 128
#define MM 64
#define IJ (MM * MM)
#define BASIS 5

// Scratch (static __device__ — no allocations allowed)
__device__ float g_mc[NN * DD * MM];   // mean over rows i  -> [n][d][j]
__device__ float g_dg[NN * DD * MM];   // diagonal          -> [n][d][t]
__device__ float g_md[NN * DD];        // mean of diag
__device__ float g_ma[NN * DD];        // mean of all
__device__ float g_c0[DD * SS];        // coeffs[d][s][0]  (mean_cols op1)
__device__ float g_c1[DD * SS];        // coeffs[d][s][1]  (identity, main GEMM)
__device__ float g_c2[DD * SS];        // coeffs[d][s][2]  (diag op3)
__device__ float g_c3[DD * SS];        // coeffs[d][s][3]  (mean_diag op4)
__device__ float g_c4[DD * SS];        // coeffs[d][s][4]  (mean_all op5)
__device__ float g_V [NN * SS * MM];   // V[n][s][t]
__device__ float g_B [NN * SS];        // B[n][s] (includes bias)

// ---------------------------------------------------------------------------
// Kernel 0: unpack the 5 basis planes into contiguous [d][s] arrays
// ---------------------------------------------------------------------------
__global__ void pack_coeffs_kernel(const float* __restrict__ coeffs) {
    int idx = blockIdx.x * blockDim.x + threadIdx.x;  // over D*S
    if (idx < DD * SS) {
        const float* c = coeffs + (size_t)idx * BASIS;
        g_c0[idx] = c[0];
        g_c1[idx] = c[1];
        g_c2[idx] = c[2];
        g_c3[idx] = c[3];
        g_c4[idx] = c[4];
    }
}

// ---------------------------------------------------------------------------
// Kernel 1: per-(n,d) reductions. One block per (n,d), 64 threads (one per col)
// ---------------------------------------------------------------------------
__global__ __launch_bounds__(64) void reduce_kernel(const float* __restrict__ X) {
    int nd = blockIdx.x;
    const float* x = X + (size_t)nd * IJ;
    int j = threadIdx.x;

    float s = 0.f;
#pragma unroll 8
    for (int i = 0; i < MM; i++) s += x[i * MM + j];   // coalesced per row
    float mc = s * (1.0f / MM);
    float dg = x[j * MM + j];

    g_mc[nd * MM + j] = mc;
    g_dg[nd * MM + j] = dg;

    __shared__ float sh1[64], sh2[64];
    sh1[j] = dg;
    sh2[j] = mc;
    __syncthreads();
#pragma unroll
    for (int off = 32; off > 0; off >>= 1) {
        if (j < off) { sh1[j] += sh1[j + off]; sh2[j] += sh2[j + off]; }
        __syncthreads();
    }
    if (j == 0) {
        g_md[nd] = sh1[0] * (1.0f / MM);
        g_ma[nd] = sh2[0] * (1.0f / MM);
    }
}

// ---------------------------------------------------------------------------
// Kernel 2: V[n,s,t] = sum_d c0[d,s]*mc[n,d,t] + c2[d,s]*dg[n,d,t]
// Grid (8 s-tiles, N). Block 256 = 64 t x 4 s-groups; each thread does 4 s.
// Coeff slabs cached in smem; mc/dg loads coalesced (L1 serves 4x s-group reuse)
// ---------------------------------------------------------------------------
__global__ __launch_bounds__(256) void v_kernel() {
    const int st0 = blockIdx.x * 16;           // s-tile base (16 s per block)
    const int n   = blockIdx.y;
    const int tid = threadIdx.x;
    const int t   = tid & 63;                  // column 0..63
    const int sg  = tid >> 6;                  // s-group 0..3 -> s = st0+sg*4..+3

    __shared__ float c0s[32][16];
    __shared__ float c2s[32][16];

    const float* mc = g_mc + (size_t)n * DD * MM;
    const float* dg = g_dg + (size_t)n * DD * MM;

    float acc[4] = {0.f, 0.f, 0.f, 0.f};

    for (int d0 = 0; d0 < DD; d0 += 32) {
        __syncthreads();
        // load coeff slabs: 32 rows x 16 s, as float4 (128 float4 per plane)
        {
            int r = tid >> 2, c = tid & 3;     // tid 0..127 covers plane
            if (tid < 128) {
                *(float4*)&c0s[r][c * 4] = *(const float4*)&g_c0[(d0 + r) * SS + st0 + c * 4];
            } else {
                int tid2 = tid - 128;
                int r2 = tid2 >> 2, c2 = tid2 & 3;
                *(float4*)&c2s[r2][c2 * 4] = *(const float4*)&g_c2[(d0 + r2) * SS + st0 + c2 * 4];
            }
        }
        __syncthreads();
#pragma unroll 8
        for (int dd = 0; dd < 32; dd++) {
            float mcv = mc[(d0 + dd) * MM + t];
            float dgv = dg[(d0 + dd) * MM + t];
#pragma unroll
            for (int q = 0; q < 4; q++)
                acc[q] += c0s[dd][sg * 4 + q] * mcv + c2s[dd][sg * 4 + q] * dgv;
        }
    }

#pragma unroll
    for (int q = 0; q < 4; q++) {
        int s = st0 + sg * 4 + q;
        g_V[(size_t)(n * SS + s) * MM + t] = acc[q];
    }
}

// ---------------------------------------------------------------------------
// Kernel 3: B[n,s] = sum_d c3[d,s]*md[n,d] + c4[d,s]*ma[n,d]  + bias[s]
// Grid N, 128 threads (s). Coalesced c3/c4, broadcast md/ma.
// ---------------------------------------------------------------------------
__global__ __launch_bounds__(128) void b_kernel(const float* __restrict__ bias) {
    const int n = blockIdx.x;
    const int s = threadIdx.x;
    float acc = 0.f;
#pragma unroll 8
    for (int d = 0; d < DD; d++) {
        acc += g_c3[d * SS + s] * g_md[n * DD + d] + g_c4[d * SS + s] * g_ma[n * DD + d];
    }
    g_B[n * SS + s] = acc + bias[s];
}

// ---------------------------------------------------------------------------
// Kernel 4: main batched GEMM + epilogue.
//   out[n,s,i,j] = sum_d c1[d,s] * X[n,d,i,j] + 0.5*(V[n,s,i]+V[n,s,j]) + B[n,s]
// Block computes [S=128] x [64 j's of row i]. Grid (i=64, n=32). 128 threads.
// Thread microtile: 8 (s) x 8 (j)  -> 64 FFMA per 4 LDS.128 per k-step.
// ---------------------------------------------------------------------------
__global__ __launch_bounds__(128) void main_gemm_kernel(const float* __restrict__ X,
                                                        float* __restrict__ out) {
    const int ti = blockIdx.x;   // row index i
    const int n  = blockIdx.y;

    __shared__ float As[16][SS];  // [kk][s]  coeffs slab   (8 KB)
    __shared__ float Bs[16][MM];  // [kk][j]  X slab        (4 KB)

    const int tid = threadIdx.x;
    const int tx = tid & 7;      // j-group: j = tx*8 .. +7
    const int ty = tid >> 3;     // s-group: s = ty*8 .. +7

    float acc[8][8];
#pragma unroll
    for (int m = 0; m < 8; m++)
#pragma unroll
        for (int q = 0; q < 8; q++) acc[m][q] = 0.f;

    const float* xbase = X + ((size_t)n * DD) * IJ + (size_t)ti * MM;

    for (int k0 = 0; k0 < DD; k0 += 16) {
        __syncthreads();
        // coeff slab: 16*128 floats = 512 float4, 4 per thread (contiguous)
        {
            const float4* src = (const float4*)(g_c1 + k0 * SS);
            float4* dst = (float4*)(&As[0][0]);
#pragma unroll
            for (int q = 0; q < 4; q++) dst[tid + q * 128] = src[tid + q * 128];
        }
        // X slab: 16 rows x 64 floats = 256 float4, 2 per thread
        {
#pragma unroll
            for (int q = 0; q < 2; q++) {
                int idx = tid + q * 128;
                int r = idx >> 4, c = idx & 15;
                ((float4*)&Bs[r][0])[c] = ((const float4*)(xbase + (size_t)(k0 + r) * IJ))[c];
            }
        }
        __syncthreads();

#pragma unroll
        for (int kk = 0; kk < 16; kk++) {
            float4 a0 = *(const float4*)&As[kk][ty * 8];
            float4 a1 = *(const float4*)&As[kk][ty * 8 + 4];
            float4 b0 = *(const float4*)&Bs[kk][tx * 8];
            float4 b1 = *(const float4*)&Bs[kk][tx * 8 + 4];
            float a[8] = {a0.x, a0.y, a0.z, a0.w, a1.x, a1.y, a1.z, a1.w};
            float b[8] = {b0.x, b0.y, b0.z, b0.w, b1.x, b1.y, b1.z, b1.w};
#pragma unroll
            for (int m = 0; m < 8; m++)
#pragma unroll
                for (int q = 0; q < 8; q++) acc[m][q] += a[m] * b[q];
        }
    }

    // epilogue
    const int j0 = tx * 8;
#pragma unroll
    for (int m = 0; m < 8; m++) {
        int s = ty * 8 + m;
        const float* vrow = g_V + (size_t)(n * SS + s) * MM;
        float base = 0.5f * vrow[ti] + g_B[n * SS + s];
        float4 r0, r1;
        r0.x = acc[m][0] + base + 0.5f * vrow[j0 + 0];
        r0.y = acc[m][1] + base + 0.5f * vrow[j0 + 1];
        r0.z = acc[m][2] + base + 0.5f * vrow[j0 + 2];
        r0.w = acc[m][3] + base + 0.5f * vrow[j0 + 3];
        r1.x = acc[m][4] + base + 0.5f * vrow[j0 + 4];
        r1.y = acc[m][5] + base + 0.5f * vrow[j0 + 5];
        r1.z = acc[m][6] + base + 0.5f * vrow[j0 + 6];
        r1.w = acc[m][7] + base + 0.5f * vrow[j0 + 7];
        float* o = &out[(((size_t)n * SS + s) * MM + ti) * MM + j0];
        *(float4*)o = r0;
        *(float4*)(o + 4) = r1;
    }
}

// ---------------------------------------------------------------------------
extern "C" void kernel_launch(void* const* d_in, const int* in_sizes, int n_in,
                              void* d_out, int out_size) {
    const float* X      = (const float*)d_in[0];  // [32,128,64,64]
    const float* coeffs = (const float*)d_in[1];  // [128,128,5]
    const float* bias   = (const float*)d_in[2];  // [1,128,1,1]
    float* out = (float*)d_out;

    pack_coeffs_kernel<<<(DD * SS + 255) / 256, 256>>>(coeffs);
    reduce_kernel<<<NN * DD, 64>>>(X);
    v_kernel<<<dim3(8, NN), 256>>>();
    b_kernel<<<NN, 128>>>(bias);
    main_gemm_kernel<<<dim3(MM, NN), 128>>>(X, out);
}

// round 12
// speedup vs baseline: 2.1952x; 2.1952x over previous
#include <cuda_runtime.h>
#include <cuda_bf16.h>
#include <cstdint>

#define NN 32
#define DD 128
#define SS 128
#define MM 64
#define IJ (MM * MM)
#define BASIS 5
#define NT 128        // ij tile per block for the MMA kernel

// ---------------------------------------------------------------------------
// Scratch (static __device__ — no allocations allowed)
// ---------------------------------------------------------------------------
__device__ float g_mc[NN * DD * MM];   // mean over rows i  -> [n][d][j]
__device__ float g_dg[NN * DD * MM];   // diagonal          -> [n][d][t]
__device__ float g_md[NN * DD];        // mean of diag
__device__ float g_ma[NN * DD];        // mean of all
__device__ float g_c0[DD * SS];        // coeffs[d][s][0]  ([d][s])
__device__ float g_c2[DD * SS];        // coeffs[d][s][2]  ([d][s])
__device__ float g_c3t[SS * DD];       // coeffs[.][.][3]  transposed [s][d]
__device__ float g_c4t[SS * DD];       // coeffs[.][.][4]  transposed [s][d]
__device__ __align__(16) uint32_t g_c1hi[SS * 64];  // A hi: [s][64] bf16x2 (d pairs)
__device__ __align__(16) uint32_t g_c1lo[SS * 64];  // A lo: [s][64] bf16x2
__device__ float g_V [NN * SS * MM];   // V[n][s][t]
__device__ float g_B [NN * SS];        // B[n][s] (includes bias)

__device__ __forceinline__ uint32_t smem_to_u32(const void* p) {
    uint32_t a;
    asm("{ .reg .u64 t; cvta.to.shared.u64 t, %1; cvt.u32.u64 %0, t; }" : "=r"(a) : "l"(p));
    return a;
}
__device__ __forceinline__ uint32_t pack_bf16x2(__nv_bfloat16 a, __nv_bfloat16 b) {
    __nv_bfloat162 t = __halves2bfloat162(a, b);   // a -> low half
    return *reinterpret_cast<uint32_t*>(&t);
}

// ---------------------------------------------------------------------------
// Kernel 0: pack coefficient planes
// ---------------------------------------------------------------------------
__global__ void pack_coeffs_kernel(const float* __restrict__ coeffs) {
    int idx = blockIdx.x * blockDim.x + threadIdx.x;
    if (idx < DD * SS) {
        int d = idx / SS, s = idx % SS;
        const float* c = coeffs + (size_t)idx * BASIS;
        g_c0[idx] = c[0];
        g_c2[idx] = c[2];
        g_c3t[s * DD + d] = c[3];
        g_c4t[s * DD + d] = c[4];
    }
    // A operand hi/lo split: idx over SS*64 (s, d-pair)
    if (idx < SS * 64) {
        int s = idx >> 6, dp = idx & 63, d = 2 * dp;
        float a = coeffs[((size_t)(d * SS + s)) * BASIS + 1];
        float b = coeffs[((size_t)((d + 1) * SS + s)) * BASIS + 1];
        __nv_bfloat16 ha = __float2bfloat16(a);
        __nv_bfloat16 hb = __float2bfloat16(b);
        __nv_bfloat16 la = __float2bfloat16(a - __bfloat162float(ha));
        __nv_bfloat16 lb = __float2bfloat16(b - __bfloat162float(hb));
        g_c1hi[idx] = pack_bf16x2(ha, hb);
        g_c1lo[idx] = pack_bf16x2(la, lb);
    }
}

// ---------------------------------------------------------------------------
// Kernel 1: per-(n,d) reductions
// ---------------------------------------------------------------------------
__global__ __launch_bounds__(64) void reduce_kernel(const float* __restrict__ X) {
    int nd = blockIdx.x;
    const float* x = X + (size_t)nd * IJ;
    int j = threadIdx.x;

    float s = 0.f;
#pragma unroll 8
    for (int i = 0; i < MM; i++) s += x[i * MM + j];
    float mc = s * (1.0f / MM);
    float dg = x[j * MM + j];

    g_mc[nd * MM + j] = mc;
    g_dg[nd * MM + j] = dg;

    __shared__ float sh1[64], sh2[64];
    sh1[j] = dg;
    sh2[j] = mc;
    __syncthreads();
#pragma unroll
    for (int off = 32; off > 0; off >>= 1) {
        if (j < off) { sh1[j] += sh1[j + off]; sh2[j] += sh2[j + off]; }
        __syncthreads();
    }
    if (j == 0) {
        g_md[nd] = sh1[0] * (1.0f / MM);
        g_ma[nd] = sh2[0] * (1.0f / MM);
    }
}

// ---------------------------------------------------------------------------
// Kernel 2: V[n,s,t] = sum_d c0[d,s]*mc[n,d,t] + c2[d,s]*dg[n,d,t]
// ---------------------------------------------------------------------------
__global__ __launch_bounds__(256) void v_kernel() {
    const int st0 = blockIdx.x * 16;
    const int n   = blockIdx.y;
    const int tid = threadIdx.x;
    const int t   = tid & 63;
    const int sg  = tid >> 6;

    __shared__ float c0s[32][16];
    __shared__ float c2s[32][16];

    const float* mc = g_mc + (size_t)n * DD * MM;
    const float* dg = g_dg + (size_t)n * DD * MM;

    float acc[4] = {0.f, 0.f, 0.f, 0.f};

    for (int d0 = 0; d0 < DD; d0 += 32) {
        __syncthreads();
        {
            int r = tid >> 2, c = tid & 3;
            if (tid < 128) {
                *(float4*)&c0s[r][c * 4] = *(const float4*)&g_c0[(d0 + r) * SS + st0 + c * 4];
            } else {
                int t2 = tid - 128;
                int r2 = t2 >> 2, c2 = t2 & 3;
                *(float4*)&c2s[r2][c2 * 4] = *(const float4*)&g_c2[(d0 + r2) * SS + st0 + c2 * 4];
            }
        }
        __syncthreads();
#pragma unroll 8
        for (int dd = 0; dd < 32; dd++) {
            float mcv = mc[(d0 + dd) * MM + t];
            float dgv = dg[(d0 + dd) * MM + t];
#pragma unroll
            for (int q = 0; q < 4; q++)
                acc[q] += c0s[dd][sg * 4 + q] * mcv + c2s[dd][sg * 4 + q] * dgv;
        }
    }

#pragma unroll
    for (int q = 0; q < 4; q++) {
        int s = st0 + sg * 4 + q;
        g_V[(size_t)(n * SS + s) * MM + t] = acc[q];
    }
}

// ---------------------------------------------------------------------------
// Kernel 3: B[n,s] — one warp per (n,s), lanes over d, shuffle reduce
// ---------------------------------------------------------------------------
__global__ __launch_bounds__(128) void b_kernel(const float* __restrict__ bias) {
    int n = blockIdx.y;
    int s = blockIdx.x * 4 + (threadIdx.x >> 5);
    int l = threadIdx.x & 31;
    const float* c3 = g_c3t + (size_t)s * DD;
    const float* c4 = g_c4t + (size_t)s * DD;
    const float* md = g_md + (size_t)n * DD;
    const float* ma = g_ma + (size_t)n * DD;
    float acc = 0.f;
#pragma unroll
    for (int k = 0; k < 4; k++) {
        int d = k * 32 + l;
        acc += c3[d] * md[d] + c4[d] * ma[d];
    }
#pragma unroll
    for (int off = 16; off > 0; off >>= 1) acc += __shfl_xor_sync(0xffffffffu, acc, off);
    if (l == 0) g_B[n * SS + s] = acc + bias[s];
}

// ---------------------------------------------------------------------------
// Kernel 4: warp-level HMMA bf16x3 split GEMM + fused epilogue.
//   D[s, ij] = Chi*Xhi + Clo*Xhi + Chi*Xlo   (fp32 accum in registers)
// Block: one (n, 128-ij tile), 256 thr = 8 warps (2 s x 4 ij), warp 64x32.
// smem rows padded to 272B (4-bank shift/row -> conflict-free ldmatrix).
// ---------------------------------------------------------------------------
#define ROWB 272                      // bytes per smem row (136 bf16)
#define SM_AHI 0
#define SM_ALO 34816
#define SM_BHI 69632
#define SM_BLO 104448
#define SMEM_SZ 139264

__device__ __forceinline__ void ldsm_x4(uint32_t* r, uint32_t addr) {
    asm volatile("ldmatrix.sync.aligned.m8n8.x4.shared.b16 {%0,%1,%2,%3}, [%4];"
                 : "=r"(r[0]), "=r"(r[1]), "=r"(r[2]), "=r"(r[3]) : "r"(addr));
}
__device__ __forceinline__ void ldsm_x2t(uint32_t* r, uint32_t addr) {
    asm volatile("ldmatrix.sync.aligned.m8n8.x2.trans.shared.b16 {%0,%1}, [%2];"
                 : "=r"(r[0]), "=r"(r[1]) : "r"(addr));
}
__device__ __forceinline__ void mma16816(float* d, const uint32_t* a, const uint32_t* b) {
    asm volatile("mma.sync.aligned.m16n8k16.row.col.f32.bf16.bf16.f32 "
                 "{%0,%1,%2,%3}, {%4,%5,%6,%7}, {%8,%9}, {%0,%1,%2,%3};"
                 : "+f"(d[0]), "+f"(d[1]), "+f"(d[2]), "+f"(d[3])
                 : "r"(a[0]), "r"(a[1]), "r"(a[2]), "r"(a[3]), "r"(b[0]), "r"(b[1]));
}

__global__ __launch_bounds__(256) void main_hmma_kernel(const float* __restrict__ X,
                                                        float* __restrict__ out) {
    extern __shared__ char smem[];
    const int tid  = threadIdx.x;
    const int lane = tid & 31;
    const int warp = tid >> 5;
    const int warp_m = warp >> 2;       // 0..1 : s half
    const int warp_n = warp & 3;        // 0..3 : ij quarter
    const int tile = blockIdx.x, n = blockIdx.y;
    const int ij0 = tile * NT;

    // ---- stage A (coeff hi/lo, [s][128d] bf16) into smem ----
    {
        const uint4* ghi = (const uint4*)g_c1hi;   // 2048 uint4
        const uint4* glo = (const uint4*)g_c1lo;
#pragma unroll
        for (int k = 0; k < 8; k++) {
            int e = tid + k * 256;
            int s = e >> 4, c = (e & 15) * 4;
            uint4 v = ghi[e];
            uint32_t* dh = (uint32_t*)(smem + SM_AHI + s * ROWB) + c;
            dh[0] = v.x; dh[1] = v.y; dh[2] = v.z; dh[3] = v.w;
            uint4 w = glo[e];
            uint32_t* dl = (uint32_t*)(smem + SM_ALO + s * ROWB) + c;
            dl[0] = w.x; dl[1] = w.y; dl[2] = w.z; dl[3] = w.w;
        }
    }
    // ---- stage B (X tile split hi/lo, [d][128 ij] bf16) ----
    {
        const float* xb = X + (size_t)n * DD * IJ + ij0;
#pragma unroll
        for (int k = 0; k < 32; k++) {
            int e = tid + k * 256;           // 8192 float2s
            int d = e >> 6, cp = e & 63;
            float2 x = *(const float2*)(xb + (size_t)d * IJ + cp * 2);
            __nv_bfloat16 h0 = __float2bfloat16(x.x);
            __nv_bfloat16 h1 = __float2bfloat16(x.y);
            __nv_bfloat16 l0 = __float2bfloat16(x.x - __bfloat162float(h0));
            __nv_bfloat16 l1 = __float2bfloat16(x.y - __bfloat162float(h1));
            *(uint32_t*)(smem + SM_BHI + d * ROWB + cp * 4) = pack_bf16x2(h0, h1);
            *(uint32_t*)(smem + SM_BLO + d * ROWB + cp * 4) = pack_bf16x2(l0, l1);
        }
    }
    __syncthreads();

    // ---- per-lane ldmatrix base addresses ----
    const uint32_t sb = smem_to_u32(smem);
    uint32_t aBase[4], bBase[4];
#pragma unroll
    for (int mt = 0; mt < 4; mt++)
        aBase[mt] = sb + SM_AHI + (uint32_t)(warp_m * 64 + mt * 16 + (lane & 15)) * ROWB
                  + (uint32_t)(lane >> 4) * 16;
#pragma unroll
    for (int nt = 0; nt < 4; nt++)
        bBase[nt] = sb + SM_BHI + (uint32_t)(lane & 15) * ROWB
                  + (uint32_t)(warp_n * 32 + nt * 8) * 2;

    float acc[4][4][4];
#pragma unroll
    for (int mt = 0; mt < 4; mt++)
#pragma unroll
        for (int nt = 0; nt < 4; nt++)
#pragma unroll
            for (int q = 0; q < 4; q++) acc[mt][nt][q] = 0.f;

    // ---- 3 passes: (Ahi,Bhi), (Alo,Bhi), (Ahi,Blo) ----
#pragma unroll
    for (int pass = 0; pass < 3; pass++) {
        const uint32_t aOff = (pass == 1) ? (SM_ALO - SM_AHI) : 0u;
        const uint32_t bOff = (pass == 2) ? (SM_BLO - SM_BHI) : 0u;
#pragma unroll
        for (int k0 = 0; k0 < 8; k0++) {
            uint32_t af[4][4], bf[4][2];
#pragma unroll
            for (int mt = 0; mt < 4; mt++)
                ldsm_x4(af[mt], aBase[mt] + aOff + k0 * 32);
#pragma unroll
            for (int nt = 0; nt < 4; nt++)
                ldsm_x2t(bf[nt], bBase[nt] + bOff + k0 * 16 * ROWB);
#pragma unroll
            for (int mt = 0; mt < 4; mt++)
#pragma unroll
                for (int nt = 0; nt < 4; nt++)
                    mma16816(acc[mt][nt], af[mt], bf[nt]);
        }
    }

    // ---- fused epilogue ----
    const float* Vn = g_V + (size_t)n * SS * MM;
    const float* Bn = g_B + n * SS;
    const int i_w = tile * 2 + (warp_n >> 1);      // output row i (fixed per warp)
    const int jb  = (warp_n & 1) * 32;             // j base for this warp

#pragma unroll
    for (int mt = 0; mt < 4; mt++) {
        int s0 = warp_m * 64 + mt * 16 + (lane >> 2);
        int s1 = s0 + 8;
        const float* v0 = Vn + s0 * MM;
        const float* v1 = Vn + s1 * MM;
        float e0 = fmaf(0.5f, v0[i_w], Bn[s0]);
        float e1 = fmaf(0.5f, v1[i_w], Bn[s1]);
        float* o0 = out + (((size_t)(n * SS + s0)) * MM + i_w) * MM;
        float* o1 = out + (((size_t)(n * SS + s1)) * MM + i_w) * MM;
#pragma unroll
        for (int nt = 0; nt < 4; nt++) {
            int j = jb + nt * 8 + 2 * (lane & 3);
            float2 r0, r1;
            r0.x = acc[mt][nt][0] + e0 + 0.5f * v0[j];
            r0.y = acc[mt][nt][1] + e0 + 0.5f * v0[j + 1];
            r1.x = acc[mt][nt][2] + e1 + 0.5f * v1[j];
            r1.y = acc[mt][nt][3] + e1 + 0.5f * v1[j + 1];
            *(float2*)(o0 + j) = r0;
            *(float2*)(o1 + j) = r1;
        }
    }
}

// ---------------------------------------------------------------------------
extern "C" void kernel_launch(void* const* d_in, const int* in_sizes, int n_in,
                              void* d_out, int out_size) {
    const float* X      = (const float*)d_in[0];  // [32,128,64,64]
    const float* coeffs = (const float*)d_in[1];  // [128,128,5]
    const float* bias   = (const float*)d_in[2];  // [1,128,1,1]
    float* out = (float*)d_out;

    cudaFuncSetAttribute(main_hmma_kernel, cudaFuncAttributeMaxDynamicSharedMemorySize, SMEM_SZ);

    pack_coeffs_kernel<<<(DD * SS + 255) / 256, 256>>>(coeffs);
    reduce_kernel<<<NN * DD, 64>>>(X);
    v_kernel<<<dim3(8, NN), 256>>>();
    b_kernel<<<dim3(SS / 4, NN), 128>>>(bias);
    main_hmma_kernel<<<dim3(IJ / NT, NN), 256, SMEM_SZ>>>(X, out);
}